// round 4
// baseline (speedup 1.0000x reference)
#include <cuda_runtime.h>
#include <math.h>

#define NB 512
#define EPSF 1e-20f
#define BN_EPSF 1e-5f
#define INV_ATTN 0.35355339059327373f   // 1/sqrt(8)

// exp matched to the reference (CPU / correctly-rounded) in the regime where
// squash is ulp-sensitive. For n < 0.05 an fp32 Taylor evaluated as
// 1 + (n + n^2*p(n)) is correctly rounded — identical to Eigen pexp / glibc
// expf there. Above 0.05 the squash cancellation amplifier is gone and
// expf's 1-2 ulp error is harmless (<3e-6 relative).
__device__ __forceinline__ float exp_matched(float n) {
    if (n < 0.05f) {
        float p = fmaf(n, 1.0f / 120.0f, 1.0f / 24.0f);
        p = fmaf(p, n, 1.0f / 6.0f);
        p = fmaf(p, n, 0.5f);
        float s = fmaf(n * n, p, n);       // n + n^2/2 + ... + n^5/120
        return 1.0f + s;
    }
    return expf(n);
}

// ---------------- scratch (static device globals; no allocs) ----------------
__device__ float g_h1[NB * 128 * 19 * 19];   // conv1 out, [b][ci][p19x19]
__device__ float g_h2[NB * 81 * 256];        // conv2 out, [b][p9x9][co]
__device__ float g_wT[1152 * 256];           // conv2 weights transposed: [ci*9+k][co]
__device__ float g_u[NB * 256];              // primary caps after squash, [b][32*8]

// ---------------- conv1 + bn + relu ----------------
__global__ void conv1_kernel(const float* __restrict__ x,
                             const float* __restrict__ w,
                             const float* __restrict__ cb,
                             const float* __restrict__ g, const float* __restrict__ bb,
                             const float* __restrict__ m, const float* __restrict__ v)
{
    int co = blockIdx.x, b = blockIdx.y, tid = threadIdx.x;
    __shared__ float s_in[39 * 39];
    const float* xb = x + b * 1521;
    for (int i = tid; i < 1521; i += 384) s_in[i] = xb[i];

    float wr[9];
#pragma unroll
    for (int k = 0; k < 9; ++k) wr[k] = w[co * 9 + k];
    float inv = g[co] / sqrtf(v[co] + BN_EPSF);
    float beta = bb[co] - m[co] * inv;
    float bias = cb[co];
    __syncthreads();

    if (tid < 361) {
        int oy = tid / 19, ox = tid % 19;
        float acc = 0.0f;
#pragma unroll
        for (int kh = 0; kh < 3; ++kh)
#pragma unroll
            for (int kw = 0; kw < 3; ++kw)
                acc = fmaf(s_in[(oy * 2 + kh) * 39 + ox * 2 + kw], wr[kh * 3 + kw], acc);
        float y = (acc + bias) * inv + beta;
        g_h1[(b * 128 + co) * 361 + tid] = y > 0.0f ? y : 0.0f;
    }
}

// ---------------- transpose conv2 weights ----------------
__global__ void wtrans_kernel(const float* __restrict__ w2)
{
    int idx = blockIdx.x * 256 + threadIdx.x;   // over 1152*256
    int row = idx / 256;     // ci*9+k
    int co  = idx % 256;
    g_wT[row * 256 + co] = w2[co * 1152 + row];
}

// ---------------- conv2 + bn + relu ----------------
__global__ void __launch_bounds__(256) conv2_kernel(
    const float* __restrict__ cb,
    const float* __restrict__ g, const float* __restrict__ bb,
    const float* __restrict__ m, const float* __restrict__ v)
{
    int b = blockIdx.x, co = threadIdx.x;
    __shared__ float s_in[8 * 361];

    float acc[81];
#pragma unroll
    for (int i = 0; i < 81; ++i) acc[i] = 0.0f;

    const float* h1b = g_h1 + b * 128 * 361;

    for (int ci0 = 0; ci0 < 128; ci0 += 8) {
        __syncthreads();
        const float* src = h1b + ci0 * 361;
        for (int i = co; i < 8 * 361; i += 256) s_in[i] = src[i];
        __syncthreads();

#pragma unroll
        for (int cc = 0; cc < 8; ++cc) {
            float wr[9];
            const float* wp = g_wT + ((ci0 + cc) * 9) * 256 + co;
#pragma unroll
            for (int k = 0; k < 9; ++k) wr[k] = wp[k * 256];
            const float* sp = s_in + cc * 361;
#pragma unroll
            for (int oy = 0; oy < 9; ++oy) {
#pragma unroll
                for (int kh = 0; kh < 3; ++kh) {
                    const float* row = sp + (oy * 2 + kh) * 19;
                    float r[19];
#pragma unroll
                    for (int i = 0; i < 19; ++i) r[i] = row[i];
#pragma unroll
                    for (int ox = 0; ox < 9; ++ox) {
#pragma unroll
                        for (int kx = 0; kx < 3; ++kx)
                            acc[oy * 9 + ox] = fmaf(r[ox * 2 + kx], wr[kh * 3 + kx], acc[oy * 9 + ox]);
                    }
                }
            }
        }
    }

    float inv = g[co] / sqrtf(v[co] + BN_EPSF);
    float beta = bb[co] - m[co] * inv;
    float bias = cb[co];
    float* outb = g_h2 + b * 81 * 256;
#pragma unroll
    for (int p = 0; p < 81; ++p) {
        float y = (acc[p] + bias) * inv + beta;
        outb[p * 256 + co] = y > 0.0f ? y : 0.0f;
    }
}

// ---------------- conv3 (depthwise 9x9) + squash -> primary caps ----------------
__global__ void conv3_kernel(const float* __restrict__ w3, const float* __restrict__ b3)
{
    int b = blockIdx.x, c = threadIdx.x;
    const float* h2b = g_h2 + b * 81 * 256;
    float acc = 0.0f;
#pragma unroll
    for (int p = 0; p < 81; ++p)
        acc = fmaf(h2b[p * 256 + c], w3[c * 81 + p], acc);
    acc += b3[c];

    // squash over groups of 8 channels
    float sq = acc * acc;
    sq += __shfl_xor_sync(0xffffffffu, sq, 4);
    sq += __shfl_xor_sync(0xffffffffu, sq, 2);
    sq += __shfl_xor_sync(0xffffffffu, sq, 1);
    float nrm = sqrtf(sq);
    float t1 = 1.0f - 1.0f / (exp_matched(nrm) + EPSF);
    g_u[b * 256 + c] = t1 * (acc / (nrm + EPSF));
}

// ---------------- fccaps x3 ----------------
__device__ __forceinline__ void fccaps_layer(
    int nl, int nh, int dl, int dh, const float* __restrict__ W,
    float* sU, float* sUhat, float* sS, float* sA, int tid)
{
    // U_hat[i][k][l] = sum_j U[i][j]*W[i][k][j][l]
    int tot = nl * nh * dh;
    for (int idx = tid; idx < tot; idx += 256) {
        int i = idx / (nh * dh);
        int r = idx % (nh * dh);
        int k = r / dh, l = r % dh;
        const float* wp = W + ((i * nh + k) * dl) * dh + l;
        float a = 0.0f;
        for (int j = 0; j < dl; ++j) a = fmaf(sU[i * dl + j], wp[j * dh], a);
        sUhat[idx] = a;
    }
    __syncthreads();
    // S[k][l] = sum_i U_hat[i][k][l]
    for (int idx = tid; idx < nh * dh; idx += 256) {
        int k = idx / dh, l = idx % dh;
        float s = 0.0f;
        for (int i = 0; i < nl; ++i) s += sUhat[(i * nh + k) * dh + l];
        sS[idx] = s;
    }
    __syncthreads();
    // A_sum[i][k] = sum_l S[k][l]*U_hat[i][k][l], scaled
    for (int idx = tid; idx < nl * nh; idx += 256) {
        int i = idx / nh, k = idx % nh;
        float a = 0.0f;
        for (int l = 0; l < dh; ++l) a = fmaf(sS[k * dh + l], sUhat[(i * nh + k) * dh + l], a);
        sA[idx] = a * INV_ATTN;
    }
    __syncthreads();
    // softmax over k per i (insensitive: plain expf)
    if (tid < nl) {
        float mx = -1e30f;
        for (int k = 0; k < nh; ++k) mx = fmaxf(mx, sA[tid * nh + k]);
        float s = 0.0f;
        for (int k = 0; k < nh; ++k) { float e = expf(sA[tid * nh + k] - mx); sA[tid * nh + k] = e; s += e; }
        float is = 1.0f / s;
        for (int k = 0; k < nh; ++k) sA[tid * nh + k] *= is;
    }
    __syncthreads();
    // U_next[k][l] = sum_i C[i][k]*U_hat[i][k][l]
    for (int idx = tid; idx < nh * dh; idx += 256) {
        int k = idx / dh, l = idx % dh;
        float a = 0.0f;
        for (int i = 0; i < nl; ++i) a = fmaf(sA[i * nh + k], sUhat[(i * nh + k) * dh + l], a);
        sS[idx] = a;
    }
    __syncthreads();
    // squash rows -> sU; sensitive: exp_matched
    for (int idx = tid; idx < nh * dh; idx += 256) {
        int k = idx / dh;
        float nsq = 0.0f;
        for (int l = 0; l < dh; ++l) { float t = sS[k * dh + l]; nsq = fmaf(t, t, nsq); }
        float nrm = sqrtf(nsq);
        float t1 = 1.0f - 1.0f / (exp_matched(nrm) + EPSF);
        sU[idx] = t1 * (sS[idx] / (nrm + EPSF));
    }
    __syncthreads();
}

__global__ void caps_kernel(const float* __restrict__ W1,
                            const float* __restrict__ W2,
                            const float* __restrict__ W3,
                            float* __restrict__ out)
{
    int b = blockIdx.x, tid = threadIdx.x;
    __shared__ float sU[512];
    __shared__ float sUhat[8192];
    __shared__ float sS[512];
    __shared__ float sA[1024];

    sU[tid] = g_u[b * 256 + tid];
    sU[256 + tid] = 0.0f;
    __syncthreads();

    fccaps_layer(32, 32, 8, 8, W1, sU, sUhat, sS, sA, tid);
    fccaps_layer(32, 32, 8, 8, W2, sU, sUhat, sS, sA, tid);
    fccaps_layer(32, 10, 8, 16, W3, sU, sUhat, sS, sA, tid);

    if (tid < 160) out[b * 160 + tid] = sU[tid];
}

// ---------------- launch ----------------
extern "C" void kernel_launch(void* const* d_in, const int* in_sizes, int n_in,
                              void* d_out, int out_size)
{
    const float* x       = (const float*)d_in[0];
    const float* conv1_w = (const float*)d_in[1];
    const float* conv1_b = (const float*)d_in[2];
    const float* bn1_g   = (const float*)d_in[3];
    const float* bn1_b   = (const float*)d_in[4];
    const float* bn1_m   = (const float*)d_in[5];
    const float* bn1_v   = (const float*)d_in[6];
    const float* conv2_w = (const float*)d_in[7];
    const float* conv2_b = (const float*)d_in[8];
    const float* bn2_g   = (const float*)d_in[9];
    const float* bn2_b   = (const float*)d_in[10];
    const float* bn2_m   = (const float*)d_in[11];
    const float* bn2_v   = (const float*)d_in[12];
    const float* conv3_w = (const float*)d_in[13];
    const float* conv3_b = (const float*)d_in[14];
    const float* W1      = (const float*)d_in[15];
    const float* W2      = (const float*)d_in[16];
    const float* W3      = (const float*)d_in[17];
    float* out = (float*)d_out;

    conv1_kernel<<<dim3(128, NB), 384>>>(x, conv1_w, conv1_b, bn1_g, bn1_b, bn1_m, bn1_v);
    wtrans_kernel<<<1152, 256>>>(conv2_w);
    conv2_kernel<<<NB, 256>>>(conv2_b, bn2_g, bn2_b, bn2_m, bn2_v);
    conv3_kernel<<<NB, 256>>>(conv3_w, conv3_b);
    caps_kernel<<<NB, 256>>>(W1, W2, W3, out);
}

// round 8
// speedup vs baseline: 1.2840x; 1.2840x over previous
#include <cuda_runtime.h>
#include <cuda_bf16.h>
#include <math.h>
#include <stdint.h>

#define NB 512
#define EPSF 1e-20f
#define BN_EPSF 1e-5f
#define INV_ATTN 0.35355339059327373f   // 1/sqrt(8)

// exp matched to reference (correctly rounded small-arg Taylor; squash-sensitive regime)
__device__ __forceinline__ float exp_matched(float n) {
    if (n < 0.05f) {
        float p = fmaf(n, 1.0f / 120.0f, 1.0f / 24.0f);
        p = fmaf(p, n, 1.0f / 6.0f);
        p = fmaf(p, n, 0.5f);
        return 1.0f + fmaf(n * n, p, n);
    }
    return expf(n);
}

__device__ __forceinline__ uint32_t bfsplit_pack_hi(float x0, float x1, uint32_t& lo) {
    __nv_bfloat16 h0 = __float2bfloat16(x0), h1 = __float2bfloat16(x1);
    __nv_bfloat16 l0 = __float2bfloat16(x0 - __bfloat162float(h0));
    __nv_bfloat16 l1 = __float2bfloat16(x1 - __bfloat162float(h1));
    lo = (uint32_t)__bfloat16_as_ushort(l0) | ((uint32_t)__bfloat16_as_ushort(l1) << 16);
    return (uint32_t)__bfloat16_as_ushort(h0) | ((uint32_t)__bfloat16_as_ushort(h1) << 16);
}

// ---------------- scratch ----------------
__device__ float g_h1[NB * 128 * 19 * 19];     // conv1 out, [b][ci][19x19]
__device__ float g_h2[NB * 81 * 256];          // conv2 out, [b*81+p][co]
__device__ uint32_t g_wbh[256 * 576];          // conv2 weights bf16-hi packed k-pairs [co][k/2]
__device__ uint32_t g_wbl[256 * 576];          // bf16-lo residual
__device__ float g_u[NB * 256];                // primary caps after squash

// ---------------- conv1 + bn + relu : one block per image ----------------
__global__ void __launch_bounds__(384) conv1_kernel(
    const float* __restrict__ x, const float* __restrict__ w, const float* __restrict__ cb,
    const float* __restrict__ g, const float* __restrict__ bb,
    const float* __restrict__ m, const float* __restrict__ v)
{
    int b = blockIdx.x, tid = threadIdx.x;
    __shared__ float s_in[39 * 39];
    __shared__ float s_w[128 * 9];
    __shared__ float s_sc[128], s_sh[128];
    const float* xb = x + b * 1521;
    for (int i = tid; i < 1521; i += 384) s_in[i] = xb[i];
    for (int i = tid; i < 1152; i += 384) s_w[i] = w[i];
    if (tid < 128) {
        float inv = g[tid] / sqrtf(v[tid] + BN_EPSF);
        s_sc[tid] = inv;
        s_sh[tid] = bb[tid] - m[tid] * inv;
    }
    __syncthreads();
    if (tid < 361) {
        int oy = tid / 19, ox = tid % 19;
        float r[9];
#pragma unroll
        for (int kh = 0; kh < 3; ++kh)
#pragma unroll
            for (int kw = 0; kw < 3; ++kw)
                r[kh * 3 + kw] = s_in[(oy * 2 + kh) * 39 + ox * 2 + kw];
        float* outb = g_h1 + b * 128 * 361 + tid;
#pragma unroll 4
        for (int co = 0; co < 128; ++co) {
            float acc = 0.0f;
#pragma unroll
            for (int k = 0; k < 9; ++k) acc = fmaf(r[k], s_w[co * 9 + k], acc);
            float y = (acc + cb[co]) * s_sc[co] + s_sh[co];
            outb[co * 361] = y > 0.0f ? y : 0.0f;
        }
    }
}

// ---------------- conv2 weight prep: bf16 hi/lo split, packed k-pairs ----------------
__global__ void wtrans_kernel(const float* __restrict__ w2)
{
    int widx = blockIdx.x * 256 + threadIdx.x;   // 576 blocks -> 147456
    int n = widx / 576, kp = widx % 576;
    uint32_t lo;
    uint32_t hi = bfsplit_pack_hi(w2[n * 1152 + 2 * kp], w2[n * 1152 + 2 * kp + 1], lo);
    g_wbh[widx] = hi;
    g_wbl[widx] = lo;
}

// ---------------- conv2 as implicit GEMM on mma.sync bf16 3-term ----------------
// M=41472 (tiles of 128), N=256 (tiles of 64), K=1152 (chunks of 64).
// smem words (uint32): sAh[128*36] sAl[128*36] sBh[64*36] sBl[64*36] | tab[1152] base[128] sc/sh[128]
#define AH_OFF 0
#define AL_OFF 4608
#define BH_OFF 9216
#define BL_OFF 11520
#define TAB_OFF 13824
#define BASE_OFF 14976
#define SC_OFF 15104
#define SH_OFF 15168
#define C2_SMEM_WORDS 15232

__global__ void __launch_bounds__(256, 2) conv2_mma_kernel(
    const float* __restrict__ cb,
    const float* __restrict__ g, const float* __restrict__ bb,
    const float* __restrict__ m, const float* __restrict__ v)
{
    extern __shared__ uint32_t sm[];
    uint32_t* sAh = sm + AH_OFF;          // [128][36]
    uint32_t* sAl = sm + AL_OFF;
    uint32_t* sBh = sm + BH_OFF;          // [64][36]
    uint32_t* sBl = sm + BL_OFF;
    int*   tabi  = (int*)(sm + TAB_OFF);  // [1152]
    int*   basei = (int*)(sm + BASE_OFF); // [128]
    float* ssc   = (float*)(sm + SC_OFF);
    float* ssh   = (float*)(sm + SH_OFF);

    const int tid = threadIdx.x;
    const int w = tid >> 5, lane = tid & 31;
    const int gi = lane >> 2, ti = lane & 3;
    const int n0 = blockIdx.x * 64;
    const int mt = blockIdx.y;

    for (int k = tid; k < 1152; k += 256) {
        int ci = k / 9, r = k - ci * 9;
        tabi[k] = ci * 361 + (r / 3) * 19 + (r % 3);
    }
    for (int i = tid; i < 128; i += 256) {
        int mg = mt * 128 + i;
        int b = mg / 81, p = mg - b * 81;
        basei[i] = b * 46208 + (p / 9) * 38 + (p % 9) * 2;   // 46208 = 128*361
    }
    if (tid < 64) {
        int co = n0 + tid;
        float inv = g[co] / sqrtf(v[co] + BN_EPSF);
        ssc[tid] = inv;
        ssh[tid] = cb[co] * inv + (bb[co] - m[co] * inv);
    }
    __syncthreads();

    float d[8][4];
#pragma unroll
    for (int s = 0; s < 8; ++s)
#pragma unroll
        for (int q = 0; q < 4; ++q) d[s][q] = 0.0f;

    const int am = tid >> 1;             // A fill: this thread's m row
    const int akb = (tid & 1) * 32;      // k sub-range (32 elements = 16 words)
    const int awb = akb >> 1;            // word offset

    for (int ch = 0; ch < 18; ++ch) {
        const int k0 = ch * 64;
        // ---- fill B: 64 rows x 32 words, direct packed copy (coalesced) ----
        {
            const int kp0 = k0 >> 1;
#pragma unroll
            for (int j = 0; j < 8; ++j) {
                int idx = tid + (j << 8);
                int n = idx >> 5, kw = idx & 31;
                sBh[n * 36 + kw] = g_wbh[(n0 + n) * 576 + kp0 + kw];
                sBl[n * 36 + kw] = g_wbl[(n0 + n) * 576 + kp0 + kw];
            }
        }
        // ---- fill A: im2col gather + bf16 hi/lo split ----
        {
            const float* src = g_h1 + basei[am];
            uint32_t* dH = sAh + am * 36 + awb;
            uint32_t* dL = sAl + am * 36 + awb;
            const int* tp = tabi + k0 + akb;
#pragma unroll
            for (int j = 0; j < 16; ++j) {
                float x0 = src[tp[2 * j]];
                float x1 = src[tp[2 * j + 1]];
                uint32_t lo;
                uint32_t hi = bfsplit_pack_hi(x0, x1, lo);
                dH[j] = hi;
                dL[j] = lo;
            }
        }
        __syncthreads();

        // ---- MMA: 4 k16-steps x 8 n-subtiles x 3 terms ----
        const uint32_t* AhR = sAh + (w * 16 + gi) * 36;
        const uint32_t* AlR = sAl + (w * 16 + gi) * 36;
#pragma unroll
        for (int s16 = 0; s16 < 4; ++s16) {
            const int kw = s16 * 8;
            uint32_t ah0 = AhR[kw + ti],          ah1 = AhR[8 * 36 + kw + ti];
            uint32_t ah2 = AhR[kw + ti + 4],      ah3 = AhR[8 * 36 + kw + ti + 4];
            uint32_t al0 = AlR[kw + ti],          al1 = AlR[8 * 36 + kw + ti];
            uint32_t al2 = AlR[kw + ti + 4],      al3 = AlR[8 * 36 + kw + ti + 4];
#pragma unroll
            for (int s = 0; s < 8; ++s) {
                const int br = (s * 8 + gi) * 36 + kw;
                uint32_t bh0 = sBh[br + ti], bh1 = sBh[br + ti + 4];
                uint32_t bl0 = sBl[br + ti], bl1 = sBl[br + ti + 4];
                asm volatile(
                    "mma.sync.aligned.m16n8k16.row.col.f32.bf16.bf16.f32 "
                    "{%0,%1,%2,%3}, {%4,%5,%6,%7}, {%8,%9}, {%0,%1,%2,%3};"
                    : "+f"(d[s][0]), "+f"(d[s][1]), "+f"(d[s][2]), "+f"(d[s][3])
                    : "r"(ah0), "r"(ah1), "r"(ah2), "r"(ah3), "r"(bh0), "r"(bh1));
                asm volatile(
                    "mma.sync.aligned.m16n8k16.row.col.f32.bf16.bf16.f32 "
                    "{%0,%1,%2,%3}, {%4,%5,%6,%7}, {%8,%9}, {%0,%1,%2,%3};"
                    : "+f"(d[s][0]), "+f"(d[s][1]), "+f"(d[s][2]), "+f"(d[s][3])
                    : "r"(ah0), "r"(ah1), "r"(ah2), "r"(ah3), "r"(bl0), "r"(bl1));
                asm volatile(
                    "mma.sync.aligned.m16n8k16.row.col.f32.bf16.bf16.f32 "
                    "{%0,%1,%2,%3}, {%4,%5,%6,%7}, {%8,%9}, {%0,%1,%2,%3};"
                    : "+f"(d[s][0]), "+f"(d[s][1]), "+f"(d[s][2]), "+f"(d[s][3])
                    : "r"(al0), "r"(al1), "r"(al2), "r"(al3), "r"(bh0), "r"(bh1));
            }
        }
        __syncthreads();
    }

    // ---- epilogue: bn + relu -> g_h2[mg][co] ----
    const int mrow0 = mt * 128 + w * 16 + gi;
#pragma unroll
    for (int s = 0; s < 8; ++s) {
        int cl = s * 8 + 2 * ti;
        float sc0 = ssc[cl], sc1 = ssc[cl + 1];
        float sh0 = ssh[cl], sh1 = ssh[cl + 1];
        float v0 = d[s][0] * sc0 + sh0; v0 = v0 > 0.0f ? v0 : 0.0f;
        float v1 = d[s][1] * sc1 + sh1; v1 = v1 > 0.0f ? v1 : 0.0f;
        float v2 = d[s][2] * sc0 + sh0; v2 = v2 > 0.0f ? v2 : 0.0f;
        float v3 = d[s][3] * sc1 + sh1; v3 = v3 > 0.0f ? v3 : 0.0f;
        *(float2*)(g_h2 + (size_t)mrow0 * 256 + n0 + cl)       = make_float2(v0, v1);
        *(float2*)(g_h2 + (size_t)(mrow0 + 8) * 256 + n0 + cl) = make_float2(v2, v3);
    }
}

// ---------------- conv3 (depthwise 9x9) + squash -> primary caps ----------------
__global__ void conv3_kernel(const float* __restrict__ w3, const float* __restrict__ b3)
{
    int b = blockIdx.x, c = threadIdx.x;
    const float* h2b = g_h2 + b * 81 * 256;
    float acc = 0.0f;
#pragma unroll
    for (int p = 0; p < 81; ++p)
        acc = fmaf(h2b[p * 256 + c], w3[c * 81 + p], acc);
    acc += b3[c];

    float sq = acc * acc;
    sq += __shfl_xor_sync(0xffffffffu, sq, 4);
    sq += __shfl_xor_sync(0xffffffffu, sq, 2);
    sq += __shfl_xor_sync(0xffffffffu, sq, 1);
    float nrm = sqrtf(sq);
    float t1 = 1.0f - 1.0f / (exp_matched(nrm) + EPSF);
    g_u[b * 256 + c] = t1 * (acc / (nrm + EPSF));
}

// ---------------- fccaps x3 ----------------
__device__ __forceinline__ void fccaps_layer(
    int nl, int nh, int dl, int dh, const float* __restrict__ W,
    float* sU, float* sUhat, float* sS, float* sA, int tid)
{
    int tot = nl * nh * dh;
    for (int idx = tid; idx < tot; idx += 256) {
        int i = idx / (nh * dh);
        int r = idx % (nh * dh);
        int k = r / dh, l = r % dh;
        const float* wp = W + ((i * nh + k) * dl) * dh + l;
        float a = 0.0f;
        for (int j = 0; j < dl; ++j) a = fmaf(sU[i * dl + j], wp[j * dh], a);
        sUhat[idx] = a;
    }
    __syncthreads();
    for (int idx = tid; idx < nh * dh; idx += 256) {
        int k = idx / dh, l = idx % dh;
        float s = 0.0f;
        for (int i = 0; i < nl; ++i) s += sUhat[(i * nh + k) * dh + l];
        sS[idx] = s;
    }
    __syncthreads();
    for (int idx = tid; idx < nl * nh; idx += 256) {
        int i = idx / nh, k = idx % nh;
        float a = 0.0f;
        for (int l = 0; l < dh; ++l) a = fmaf(sS[k * dh + l], sUhat[(i * nh + k) * dh + l], a);
        sA[idx] = a * INV_ATTN;
    }
    __syncthreads();
    if (tid < nl) {
        float mx = -1e30f;
        for (int k = 0; k < nh; ++k) mx = fmaxf(mx, sA[tid * nh + k]);
        float s = 0.0f;
        for (int k = 0; k < nh; ++k) { float e = expf(sA[tid * nh + k] - mx); sA[tid * nh + k] = e; s += e; }
        float is = 1.0f / s;
        for (int k = 0; k < nh; ++k) sA[tid * nh + k] *= is;
    }
    __syncthreads();
    for (int idx = tid; idx < nh * dh; idx += 256) {
        int k = idx / dh, l = idx % dh;
        float a = 0.0f;
        for (int i = 0; i < nl; ++i) a = fmaf(sA[i * nh + k], sUhat[(i * nh + k) * dh + l], a);
        sS[idx] = a;
    }
    __syncthreads();
    for (int idx = tid; idx < nh * dh; idx += 256) {
        int k = idx / dh;
        float nsq = 0.0f;
        for (int l = 0; l < dh; ++l) { float t = sS[k * dh + l]; nsq = fmaf(t, t, nsq); }
        float nrm = sqrtf(nsq);
        float t1 = 1.0f - 1.0f / (exp_matched(nrm) + EPSF);
        sU[idx] = t1 * (sS[idx] / (nrm + EPSF));
    }
    __syncthreads();
}

__global__ void caps_kernel(const float* __restrict__ W1,
                            const float* __restrict__ W2,
                            const float* __restrict__ W3,
                            float* __restrict__ out)
{
    int b = blockIdx.x, tid = threadIdx.x;
    __shared__ float sU[512];
    __shared__ float sUhat[8192];
    __shared__ float sS[512];
    __shared__ float sA[1024];

    sU[tid] = g_u[b * 256 + tid];
    sU[256 + tid] = 0.0f;
    __syncthreads();

    fccaps_layer(32, 32, 8, 8, W1, sU, sUhat, sS, sA, tid);
    fccaps_layer(32, 32, 8, 8, W2, sU, sUhat, sS, sA, tid);
    fccaps_layer(32, 10, 8, 16, W3, sU, sUhat, sS, sA, tid);

    if (tid < 160) out[b * 160 + tid] = sU[tid];
}

// ---------------- launch ----------------
extern "C" void kernel_launch(void* const* d_in, const int* in_sizes, int n_in,
                              void* d_out, int out_size)
{
    const float* x       = (const float*)d_in[0];
    const float* conv1_w = (const float*)d_in[1];
    const float* conv1_b = (const float*)d_in[2];
    const float* bn1_g   = (const float*)d_in[3];
    const float* bn1_b   = (const float*)d_in[4];
    const float* bn1_m   = (const float*)d_in[5];
    const float* bn1_v   = (const float*)d_in[6];
    const float* conv2_w = (const float*)d_in[7];
    const float* conv2_b = (const float*)d_in[8];
    const float* bn2_g   = (const float*)d_in[9];
    const float* bn2_b   = (const float*)d_in[10];
    const float* bn2_m   = (const float*)d_in[11];
    const float* bn2_v   = (const float*)d_in[12];
    const float* conv3_w = (const float*)d_in[13];
    const float* conv3_b = (const float*)d_in[14];
    const float* W1      = (const float*)d_in[15];
    const float* W2      = (const float*)d_in[16];
    const float* W3      = (const float*)d_in[17];
    float* out = (float*)d_out;

    cudaFuncSetAttribute(conv2_mma_kernel, cudaFuncAttributeMaxDynamicSharedMemorySize,
                         C2_SMEM_WORDS * (int)sizeof(uint32_t));

    conv1_kernel<<<NB, 384>>>(x, conv1_w, conv1_b, bn1_g, bn1_b, bn1_m, bn1_v);
    wtrans_kernel<<<576, 256>>>(conv2_w);
    conv2_mma_kernel<<<dim3(4, 324), 256, C2_SMEM_WORDS * sizeof(uint32_t)>>>(
        conv2_b, bn2_g, bn2_b, bn2_m, bn2_v);
    conv3_kernel<<<NB, 256>>>(conv3_w, conv3_b);
    caps_kernel<<<NB, 256>>>(W1, W2, W3, out);
}

// round 9
// speedup vs baseline: 2.1714x; 1.6911x over previous
#include <cuda_runtime.h>
#include <cuda_bf16.h>
#include <math.h>
#include <stdint.h>

#define NB 512
#define EPSF 1e-20f
#define BN_EPSF 1e-5f
#define INV_ATTN 0.35355339059327373f   // 1/sqrt(8)

// exp matched to reference (correctly rounded small-arg Taylor; squash-sensitive regime)
__device__ __forceinline__ float exp_matched(float n) {
    if (n < 0.05f) {
        float p = fmaf(n, 1.0f / 120.0f, 1.0f / 24.0f);
        p = fmaf(p, n, 1.0f / 6.0f);
        p = fmaf(p, n, 0.5f);
        return 1.0f + fmaf(n * n, p, n);
    }
    return expf(n);
}

__device__ __forceinline__ uint32_t bfsplit_pack_hi(float x0, float x1, uint32_t& lo) {
    __nv_bfloat16 h0 = __float2bfloat16(x0), h1 = __float2bfloat16(x1);
    __nv_bfloat16 l0 = __float2bfloat16(x0 - __bfloat162float(h0));
    __nv_bfloat16 l1 = __float2bfloat16(x1 - __bfloat162float(h1));
    lo = (uint32_t)__bfloat16_as_ushort(l0) | ((uint32_t)__bfloat16_as_ushort(l1) << 16);
    return (uint32_t)__bfloat16_as_ushort(h0) | ((uint32_t)__bfloat16_as_ushort(h1) << 16);
}

__device__ __forceinline__ uint32_t smem_u32(const void* p) {
    uint32_t a;
    asm("{ .reg .u64 t; cvta.to.shared.u64 t, %1; cvt.u32.u64 %0, t; }" : "=r"(a) : "l"(p));
    return a;
}
__device__ __forceinline__ void cp_async16(uint32_t saddr, const void* gptr) {
    asm volatile("cp.async.cg.shared.global [%0], [%1], 16;" :: "r"(saddr), "l"(gptr));
}
#define CP_COMMIT() asm volatile("cp.async.commit_group;" ::: "memory")
#define CP_WAIT1()  asm volatile("cp.async.wait_group 1;" ::: "memory")
#define CP_WAIT0()  asm volatile("cp.async.wait_group 0;" ::: "memory")

// ---------------- scratch ----------------
__device__ float g_h1[NB * 128 * 19 * 19];     // conv1 out, [b][ci][19x19]
__device__ float g_h2[NB * 81 * 256];          // conv2 out, [b*81+p][co]
__device__ uint32_t g_wbh[256 * 576];          // conv2 weights bf16-hi packed k-pairs [co][k/2]
__device__ uint32_t g_wbl[256 * 576];          // bf16-lo residual
__device__ float g_u[NB * 256];                // primary caps after squash

// ---------------- conv1 + bn + relu : one block per image ----------------
__global__ void __launch_bounds__(384) conv1_kernel(
    const float* __restrict__ x, const float* __restrict__ w, const float* __restrict__ cb,
    const float* __restrict__ g, const float* __restrict__ bb,
    const float* __restrict__ m, const float* __restrict__ v)
{
    int b = blockIdx.x, tid = threadIdx.x;
    __shared__ float s_in[39 * 39];
    __shared__ float s_w[128 * 9];
    __shared__ float s_sc[128], s_sh[128];
    const float* xb = x + b * 1521;
    for (int i = tid; i < 1521; i += 384) s_in[i] = xb[i];
    for (int i = tid; i < 1152; i += 384) s_w[i] = w[i];
    if (tid < 128) {
        float inv = g[tid] / sqrtf(v[tid] + BN_EPSF);
        s_sc[tid] = inv;
        s_sh[tid] = cb[tid] * inv + (bb[tid] - m[tid] * inv);
    }
    __syncthreads();
    if (tid < 361) {
        int oy = tid / 19, ox = tid % 19;
        float r[9];
#pragma unroll
        for (int kh = 0; kh < 3; ++kh)
#pragma unroll
            for (int kw = 0; kw < 3; ++kw)
                r[kh * 3 + kw] = s_in[(oy * 2 + kh) * 39 + ox * 2 + kw];
        float* outb = g_h1 + b * 128 * 361 + tid;
#pragma unroll 4
        for (int co = 0; co < 128; ++co) {
            float acc = 0.0f;
#pragma unroll
            for (int k = 0; k < 9; ++k) acc = fmaf(r[k], s_w[co * 9 + k], acc);
            float y = acc * s_sc[co] + s_sh[co];
            outb[co * 361] = y > 0.0f ? y : 0.0f;
        }
    }
}

// ---------------- conv2 weight prep: bf16 hi/lo split, packed k-pairs ----------------
__global__ void wtrans_kernel(const float* __restrict__ w2)
{
    int widx = blockIdx.x * 256 + threadIdx.x;   // 576 blocks -> 147456
    int n = widx / 576, kp = widx % 576;
    uint32_t lo;
    uint32_t hi = bfsplit_pack_hi(w2[n * 1152 + 2 * kp], w2[n * 1152 + 2 * kp + 1], lo);
    g_wbh[widx] = hi;
    g_wbl[widx] = lo;
}

// ---------------- conv2 as implicit GEMM on mma.sync bf16 3-term, pipelined ----------------
// M=41472 (tiles of 128), N=256 (tiles of 64), K=1152 (chunks of 64).
// smem words: AH[128*36] AL[128*36] | B[2 buf][2 hl][64*36] | tab[1152] base[128] sc[64] sh[64]
#define AH_OFF 0
#define AL_OFF 4608
#define B_OFF  9216
#define TAB_OFF 18432
#define BASE_OFF 19584
#define SC_OFF 19712
#define SH_OFF 19776
#define C2_SMEM_WORDS 19840

__global__ void __launch_bounds__(256, 2) conv2_mma_kernel(
    const float* __restrict__ cb,
    const float* __restrict__ g, const float* __restrict__ bb,
    const float* __restrict__ m, const float* __restrict__ v)
{
    extern __shared__ uint32_t sm[];
    uint32_t* sAh = sm + AH_OFF;          // [128][36]
    uint32_t* sAl = sm + AL_OFF;
    int*   tabi  = (int*)(sm + TAB_OFF);  // [1152]
    int*   basei = (int*)(sm + BASE_OFF); // [128]
    float* ssc   = (float*)(sm + SC_OFF);
    float* ssh   = (float*)(sm + SH_OFF);
    const uint32_t sbase = smem_u32(sm);

    const int tid = threadIdx.x;
    const int w = tid >> 5, lane = tid & 31;
    const int gi = lane >> 2, ti = lane & 3;
    const int n0 = blockIdx.x * 64;
    const int mt = blockIdx.y;

    for (int k = tid; k < 1152; k += 256) {
        int ci = k / 9, r = k - ci * 9;
        tabi[k] = ci * 361 + (r / 3) * 19 + (r % 3);
    }
    for (int i = tid; i < 128; i += 256) {
        int mg = mt * 128 + i;
        int b = mg / 81, p = mg - b * 81;
        basei[i] = b * 46208 + (p / 9) * 38 + (p % 9) * 2;   // 46208 = 128*361
    }
    if (tid < 64) {
        int co = n0 + tid;
        float inv = g[co] / sqrtf(v[co] + BN_EPSF);
        ssc[tid] = inv;
        ssh[tid] = cb[co] * inv + (bb[co] - m[co] * inv);
    }
    __syncthreads();

    float d[8][4];
#pragma unroll
    for (int s = 0; s < 8; ++s)
#pragma unroll
        for (int q = 0; q < 4; ++q) d[s][q] = 0.0f;

    const int am = tid >> 1;             // A: this thread's m row
    const int akb = (tid & 1) * 32;      // k sub-range (32 elements)
    const int awb = akb >> 1;            // word offset

    // B cp.async slots for this thread: 4 x 16B per chunk
    // idx -> hl (hi/lo), row n, 16B segment
    const int bidx0 = tid;
    // A gather staging regs
    float fr[32];

    // ---- prologue: B(0) cp.async + A(0) gather ----
    {
#pragma unroll
        for (int j = 0; j < 4; ++j) {
            int idx = bidx0 + (j << 8);
            int hl = idx >> 9, n = (idx >> 3) & 63, seg = idx & 7;
            const uint32_t* gsrc = (hl ? g_wbl : g_wbh) + (n0 + n) * 576 + seg * 4;
            uint32_t saddr = sbase + (B_OFF + hl * 2304 + n * 36 + seg * 4) * 4;
            cp_async16(saddr, gsrc);
        }
        CP_COMMIT();
        const float* src = g_h1 + basei[am];
        const int* tp = tabi + akb;
#pragma unroll
        for (int j = 0; j < 32; ++j) fr[j] = src[tp[j]];
    }

    for (int ch = 0; ch < 18; ++ch) {
        const int buf = ch & 1;
        // ---- cvt + STS A(ch) (previous MMA finished via trailing sync) ----
        {
            uint32_t* dH = sAh + am * 36 + awb;
            uint32_t* dL = sAl + am * 36 + awb;
#pragma unroll
            for (int j = 0; j < 16; ++j) {
                uint32_t lo;
                uint32_t hi = bfsplit_pack_hi(fr[2 * j], fr[2 * j + 1], lo);
                dH[j] = hi;
                dL[j] = lo;
            }
        }
        const bool more = (ch < 17);
        if (more) {
            // ---- prefetch B(ch+1) via cp.async into other buffer ----
            const int kp0n = (ch + 1) * 32;
#pragma unroll
            for (int j = 0; j < 4; ++j) {
                int idx = bidx0 + (j << 8);
                int hl = idx >> 9, n = (idx >> 3) & 63, seg = idx & 7;
                const uint32_t* gsrc = (hl ? g_wbl : g_wbh) + (n0 + n) * 576 + kp0n + seg * 4;
                uint32_t saddr = sbase + (B_OFF + (buf ^ 1) * 4608 + hl * 2304 + n * 36 + seg * 4) * 4;
                cp_async16(saddr, gsrc);
            }
            CP_COMMIT();
            // ---- prefetch A(ch+1) gather into regs (completes under MMA) ----
            const float* src = g_h1 + basei[am];
            const int* tp = tabi + (ch + 1) * 64 + akb;
#pragma unroll
            for (int j = 0; j < 32; ++j) fr[j] = src[tp[j]];
            CP_WAIT1();
        } else {
            CP_WAIT0();
        }
        __syncthreads();

        // ---- MMA: 4 k16-steps x 8 n-subtiles x 3 terms ----
        const uint32_t* sBh = sm + B_OFF + buf * 4608;
        const uint32_t* sBl = sBh + 2304;
        const uint32_t* AhR = sAh + (w * 16 + gi) * 36;
        const uint32_t* AlR = sAl + (w * 16 + gi) * 36;
#pragma unroll
        for (int s16 = 0; s16 < 4; ++s16) {
            const int kw = s16 * 8;
            uint32_t ah0 = AhR[kw + ti],          ah1 = AhR[8 * 36 + kw + ti];
            uint32_t ah2 = AhR[kw + ti + 4],      ah3 = AhR[8 * 36 + kw + ti + 4];
            uint32_t al0 = AlR[kw + ti],          al1 = AlR[8 * 36 + kw + ti];
            uint32_t al2 = AlR[kw + ti + 4],      al3 = AlR[8 * 36 + kw + ti + 4];
#pragma unroll
            for (int s = 0; s < 8; ++s) {
                const int br = (s * 8 + gi) * 36 + kw;
                uint32_t bh0 = sBh[br + ti], bh1 = sBh[br + ti + 4];
                uint32_t bl0 = sBl[br + ti], bl1 = sBl[br + ti + 4];
                asm volatile(
                    "mma.sync.aligned.m16n8k16.row.col.f32.bf16.bf16.f32 "
                    "{%0,%1,%2,%3}, {%4,%5,%6,%7}, {%8,%9}, {%0,%1,%2,%3};"
                    : "+f"(d[s][0]), "+f"(d[s][1]), "+f"(d[s][2]), "+f"(d[s][3])
                    : "r"(ah0), "r"(ah1), "r"(ah2), "r"(ah3), "r"(bh0), "r"(bh1));
                asm volatile(
                    "mma.sync.aligned.m16n8k16.row.col.f32.bf16.bf16.f32 "
                    "{%0,%1,%2,%3}, {%4,%5,%6,%7}, {%8,%9}, {%0,%1,%2,%3};"
                    : "+f"(d[s][0]), "+f"(d[s][1]), "+f"(d[s][2]), "+f"(d[s][3])
                    : "r"(ah0), "r"(ah1), "r"(ah2), "r"(ah3), "r"(bl0), "r"(bl1));
                asm volatile(
                    "mma.sync.aligned.m16n8k16.row.col.f32.bf16.bf16.f32 "
                    "{%0,%1,%2,%3}, {%4,%5,%6,%7}, {%8,%9}, {%0,%1,%2,%3};"
                    : "+f"(d[s][0]), "+f"(d[s][1]), "+f"(d[s][2]), "+f"(d[s][3])
                    : "r"(al0), "r"(al1), "r"(al2), "r"(al3), "r"(bh0), "r"(bh1));
            }
        }
        __syncthreads();
    }

    // ---- epilogue: bn + relu -> g_h2[mg][co] ----
    const int mrow0 = mt * 128 + w * 16 + gi;
#pragma unroll
    for (int s = 0; s < 8; ++s) {
        int cl = s * 8 + 2 * ti;
        float sc0 = ssc[cl], sc1 = ssc[cl + 1];
        float sh0 = ssh[cl], sh1 = ssh[cl + 1];
        float v0 = d[s][0] * sc0 + sh0; v0 = v0 > 0.0f ? v0 : 0.0f;
        float v1 = d[s][1] * sc1 + sh1; v1 = v1 > 0.0f ? v1 : 0.0f;
        float v2 = d[s][2] * sc0 + sh0; v2 = v2 > 0.0f ? v2 : 0.0f;
        float v3 = d[s][3] * sc1 + sh1; v3 = v3 > 0.0f ? v3 : 0.0f;
        *(float2*)(g_h2 + (size_t)mrow0 * 256 + n0 + cl)       = make_float2(v0, v1);
        *(float2*)(g_h2 + (size_t)(mrow0 + 8) * 256 + n0 + cl) = make_float2(v2, v3);
    }
}

// ---------------- conv3 (depthwise 9x9) + squash -> primary caps ----------------
__global__ void conv3_kernel(const float* __restrict__ w3, const float* __restrict__ b3)
{
    int b = blockIdx.x, c = threadIdx.x;
    const float* h2b = g_h2 + b * 81 * 256;
    float acc = 0.0f;
#pragma unroll
    for (int p = 0; p < 81; ++p)
        acc = fmaf(h2b[p * 256 + c], w3[c * 81 + p], acc);
    acc += b3[c];

    float sq = acc * acc;
    sq += __shfl_xor_sync(0xffffffffu, sq, 4);
    sq += __shfl_xor_sync(0xffffffffu, sq, 2);
    sq += __shfl_xor_sync(0xffffffffu, sq, 1);
    float nrm = sqrtf(sq);
    float t1 = 1.0f - 1.0f / (exp_matched(nrm) + EPSF);
    g_u[b * 256 + c] = t1 * (acc / (nrm + EPSF));
}

// ---------------- fccaps x3 ----------------
__device__ __forceinline__ void fccaps_layer(
    int nl, int nh, int dl, int dh, const float* __restrict__ W,
    float* sU, float* sUhat, float* sS, float* sA, int tid)
{
    int tot = nl * nh * dh;
    for (int idx = tid; idx < tot; idx += 256) {
        int i = idx / (nh * dh);
        int r = idx % (nh * dh);
        int k = r / dh, l = r % dh;
        const float* wp = W + ((i * nh + k) * dl) * dh + l;
        float a = 0.0f;
        for (int j = 0; j < dl; ++j) a = fmaf(sU[i * dl + j], wp[j * dh], a);
        sUhat[idx] = a;
    }
    __syncthreads();
    for (int idx = tid; idx < nh * dh; idx += 256) {
        int k = idx / dh, l = idx % dh;
        float s = 0.0f;
        for (int i = 0; i < nl; ++i) s += sUhat[(i * nh + k) * dh + l];
        sS[idx] = s;
    }
    __syncthreads();
    for (int idx = tid; idx < nl * nh; idx += 256) {
        int i = idx / nh, k = idx % nh;
        float a = 0.0f;
        for (int l = 0; l < dh; ++l) a = fmaf(sS[k * dh + l], sUhat[(i * nh + k) * dh + l], a);
        sA[idx] = a * INV_ATTN;
    }
    __syncthreads();
    if (tid < nl) {
        float mx = -1e30f;
        for (int k = 0; k < nh; ++k) mx = fmaxf(mx, sA[tid * nh + k]);
        float s = 0.0f;
        for (int k = 0; k < nh; ++k) { float e = expf(sA[tid * nh + k] - mx); sA[tid * nh + k] = e; s += e; }
        float is = 1.0f / s;
        for (int k = 0; k < nh; ++k) sA[tid * nh + k] *= is;
    }
    __syncthreads();
    for (int idx = tid; idx < nh * dh; idx += 256) {
        int k = idx / dh, l = idx % dh;
        float a = 0.0f;
        for (int i = 0; i < nl; ++i) a = fmaf(sA[i * nh + k], sUhat[(i * nh + k) * dh + l], a);
        sS[idx] = a;
    }
    __syncthreads();
    for (int idx = tid; idx < nh * dh; idx += 256) {
        int k = idx / dh;
        float nsq = 0.0f;
        for (int l = 0; l < dh; ++l) { float t = sS[k * dh + l]; nsq = fmaf(t, t, nsq); }
        float nrm = sqrtf(nsq);
        float t1 = 1.0f - 1.0f / (exp_matched(nrm) + EPSF);
        sU[idx] = t1 * (sS[idx] / (nrm + EPSF));
    }
    __syncthreads();
}

__global__ void caps_kernel(const float* __restrict__ W1,
                            const float* __restrict__ W2,
                            const float* __restrict__ W3,
                            float* __restrict__ out)
{
    int b = blockIdx.x, tid = threadIdx.x;
    __shared__ float sU[512];
    __shared__ float sUhat[8192];
    __shared__ float sS[512];
    __shared__ float sA[1024];

    sU[tid] = g_u[b * 256 + tid];
    sU[256 + tid] = 0.0f;
    __syncthreads();

    fccaps_layer(32, 32, 8, 8, W1, sU, sUhat, sS, sA, tid);
    fccaps_layer(32, 32, 8, 8, W2, sU, sUhat, sS, sA, tid);
    fccaps_layer(32, 10, 8, 16, W3, sU, sUhat, sS, sA, tid);

    if (tid < 160) out[b * 160 + tid] = sU[tid];
}

// ---------------- launch ----------------
extern "C" void kernel_launch(void* const* d_in, const int* in_sizes, int n_in,
                              void* d_out, int out_size)
{
    const float* x       = (const float*)d_in[0];
    const float* conv1_w = (const float*)d_in[1];
    const float* conv1_b = (const float*)d_in[2];
    const float* bn1_g   = (const float*)d_in[3];
    const float* bn1_b   = (const float*)d_in[4];
    const float* bn1_m   = (const float*)d_in[5];
    const float* bn1_v   = (const float*)d_in[6];
    const float* conv2_w = (const float*)d_in[7];
    const float* conv2_b = (const float*)d_in[8];
    const float* bn2_g   = (const float*)d_in[9];
    const float* bn2_b   = (const float*)d_in[10];
    const float* bn2_m   = (const float*)d_in[11];
    const float* bn2_v   = (const float*)d_in[12];
    const float* conv3_w = (const float*)d_in[13];
    const float* conv3_b = (const float*)d_in[14];
    const float* W1      = (const float*)d_in[15];
    const float* W2      = (const float*)d_in[16];
    const float* W3      = (const float*)d_in[17];
    float* out = (float*)d_out;

    cudaFuncSetAttribute(conv2_mma_kernel, cudaFuncAttributeMaxDynamicSharedMemorySize,
                         C2_SMEM_WORDS * (int)sizeof(uint32_t));

    conv1_kernel<<<NB, 384>>>(x, conv1_w, conv1_b, bn1_g, bn1_b, bn1_m, bn1_v);
    wtrans_kernel<<<576, 256>>>(conv2_w);
    conv2_mma_kernel<<<dim3(4, 324), 256, C2_SMEM_WORDS * sizeof(uint32_t)>>>(
        conv2_b, bn2_g, bn2_b, bn2_m, bn2_v);
    conv3_kernel<<<NB, 256>>>(conv3_w, conv3_b);
    caps_kernel<<<NB, 256>>>(W1, W2, W3, out);
}

// round 10
// speedup vs baseline: 2.2470x; 1.0348x over previous
#include <cuda_runtime.h>
#include <cuda_bf16.h>
#include <math.h>
#include <stdint.h>

#define NB 512
#define EPSF 1e-20f
#define BN_EPSF 1e-5f
#define INV_ATTN 0.35355339059327373f   // 1/sqrt(8)

// exp matched to reference (correctly rounded small-arg Taylor; squash-sensitive regime)
__device__ __forceinline__ float exp_matched(float n) {
    if (n < 0.05f) {
        float p = fmaf(n, 1.0f / 120.0f, 1.0f / 24.0f);
        p = fmaf(p, n, 1.0f / 6.0f);
        p = fmaf(p, n, 0.5f);
        return 1.0f + fmaf(n * n, p, n);
    }
    return expf(n);
}

__device__ __forceinline__ uint32_t bfsplit_pack_hi(float x0, float x1, uint32_t& lo) {
    __nv_bfloat16 h0 = __float2bfloat16(x0), h1 = __float2bfloat16(x1);
    __nv_bfloat16 l0 = __float2bfloat16(x0 - __bfloat162float(h0));
    __nv_bfloat16 l1 = __float2bfloat16(x1 - __bfloat162float(h1));
    lo = (uint32_t)__bfloat16_as_ushort(l0) | ((uint32_t)__bfloat16_as_ushort(l1) << 16);
    return (uint32_t)__bfloat16_as_ushort(h0) | ((uint32_t)__bfloat16_as_ushort(h1) << 16);
}

__device__ __forceinline__ uint32_t smem_u32(const void* p) {
    uint32_t a;
    asm("{ .reg .u64 t; cvta.to.shared.u64 t, %1; cvt.u32.u64 %0, t; }" : "=r"(a) : "l"(p));
    return a;
}
__device__ __forceinline__ void cp_async16(uint32_t saddr, const void* gptr) {
    asm volatile("cp.async.cg.shared.global [%0], [%1], 16;" :: "r"(saddr), "l"(gptr));
}
#define CP_COMMIT() asm volatile("cp.async.commit_group;" ::: "memory")
#define CP_WAIT1()  asm volatile("cp.async.wait_group 1;" ::: "memory")
#define CP_WAIT0()  asm volatile("cp.async.wait_group 0;" ::: "memory")

// ---------------- scratch ----------------
__device__ float g_h1[NB * 128 * 19 * 19];     // conv1 out, [b][ci][19x19]
__device__ float g_h2[NB * 81 * 256];          // conv2 out, [b*81+p][co]
__device__ uint32_t g_wbh[256 * 576];          // conv2 weights bf16-hi packed k-pairs [co][k/2]
__device__ uint32_t g_wbl[256 * 576];          // bf16-lo residual
__device__ float g_u[NB * 256];                // primary caps after squash

// ---------------- conv1 + bn + relu : one block per image ----------------
__global__ void __launch_bounds__(384) conv1_kernel(
    const float* __restrict__ x, const float* __restrict__ w, const float* __restrict__ cb,
    const float* __restrict__ g, const float* __restrict__ bb,
    const float* __restrict__ m, const float* __restrict__ v)
{
    int b = blockIdx.x, tid = threadIdx.x;
    __shared__ float s_in[39 * 39];
    __shared__ float s_w[128 * 9];
    __shared__ float s_sc[128], s_sh[128];
    const float* xb = x + b * 1521;
    for (int i = tid; i < 1521; i += 384) s_in[i] = xb[i];
    for (int i = tid; i < 1152; i += 384) s_w[i] = w[i];
    if (tid < 128) {
        float inv = g[tid] / sqrtf(v[tid] + BN_EPSF);
        s_sc[tid] = inv;
        s_sh[tid] = cb[tid] * inv + (bb[tid] - m[tid] * inv);
    }
    __syncthreads();
    if (tid < 361) {
        int oy = tid / 19, ox = tid % 19;
        float r[9];
#pragma unroll
        for (int kh = 0; kh < 3; ++kh)
#pragma unroll
            for (int kw = 0; kw < 3; ++kw)
                r[kh * 3 + kw] = s_in[(oy * 2 + kh) * 39 + ox * 2 + kw];
        float* outb = g_h1 + b * 128 * 361 + tid;
#pragma unroll 4
        for (int co = 0; co < 128; ++co) {
            float acc = 0.0f;
#pragma unroll
            for (int k = 0; k < 9; ++k) acc = fmaf(r[k], s_w[co * 9 + k], acc);
            float y = acc * s_sc[co] + s_sh[co];
            outb[co * 361] = y > 0.0f ? y : 0.0f;
        }
    }
}

// ---------------- conv2 weight prep: bf16 hi/lo split, packed k-pairs ----------------
__global__ void wtrans_kernel(const float* __restrict__ w2)
{
    int widx = blockIdx.x * 256 + threadIdx.x;   // 576 blocks -> 147456
    int n = widx / 576, kp = widx % 576;
    uint32_t lo;
    uint32_t hi = bfsplit_pack_hi(w2[n * 1152 + 2 * kp], w2[n * 1152 + 2 * kp + 1], lo);
    g_wbh[widx] = hi;
    g_wbl[widx] = lo;
}

// ---------------- conv2 as implicit GEMM on mma.sync bf16 3-term, pipelined ----------------
// One CTA per m-tile (128 rows), full N=256. 512 threads = 16 warps:
// warp -> 16-row slab (w>>1), 128-col half (w&1); 16 n8-subtiles, 64 accums/thread.
// smem words: AH[128*36] AL[128*36] | B[2 buf][hi 256*36 | lo 256*36] | tab | base | sc | sh
#define AH_OFF 0
#define AL_OFF 4608
#define B_OFF 9216
#define B_BUF_STRIDE 18432
#define B_HL_STRIDE 9216
#define TAB_OFF 46080
#define BASE_OFF 47232
#define SC_OFF 47360
#define SH_OFF 47616
#define C2_SMEM_WORDS 47872

__global__ void __launch_bounds__(512, 1) conv2_mma_kernel(
    const float* __restrict__ cb,
    const float* __restrict__ g, const float* __restrict__ bb,
    const float* __restrict__ m, const float* __restrict__ v)
{
    extern __shared__ uint32_t sm[];
    uint32_t* sAh = sm + AH_OFF;          // [128][36]
    uint32_t* sAl = sm + AL_OFF;
    int*   tabi  = (int*)(sm + TAB_OFF);  // [1152]
    int*   basei = (int*)(sm + BASE_OFF); // [128]
    float* ssc   = (float*)(sm + SC_OFF); // [256]
    float* ssh   = (float*)(sm + SH_OFF); // [256]
    const uint32_t sbase = smem_u32(sm);

    const int tid = threadIdx.x;
    const int w = tid >> 5, lane = tid & 31;
    const int gi = lane >> 2, ti = lane & 3;
    const int mt = blockIdx.x;
    const int r0 = (w >> 1) * 16;         // row slab
    const int c0 = (w & 1) * 128;         // column half

    for (int k = tid; k < 1152; k += 512) {
        int ci = k / 9, r = k - ci * 9;
        tabi[k] = ci * 361 + (r / 3) * 19 + (r % 3);
    }
    if (tid < 128) {
        int mg = mt * 128 + tid;
        int b = mg / 81, p = mg - b * 81;
        basei[tid] = b * 46208 + (p / 9) * 38 + (p % 9) * 2;   // 46208 = 128*361
    }
    if (tid < 256) {
        float inv = g[tid] / sqrtf(v[tid] + BN_EPSF);
        ssc[tid] = inv;
        ssh[tid] = cb[tid] * inv + (bb[tid] - m[tid] * inv);
    }
    __syncthreads();

    float d[16][4];
#pragma unroll
    for (int s = 0; s < 16; ++s)
#pragma unroll
        for (int q = 0; q < 4; ++q) d[s][q] = 0.0f;

    const int am = tid >> 2;             // A: this thread's m row (0..127)
    const int akb = (tid & 3) * 16;      // k sub-range (16 elements)
    const int awb = akb >> 1;            // word offset (8 words)

    float fr[16];

    // ---- prologue: B(0) cp.async + A(0) gather ----
    {
        // B: 4096 x 16B ops total; 8 per thread
#pragma unroll
        for (int j = 0; j < 8; ++j) {
            int idx = tid + (j << 9);
            int hl = idx >> 11, n = (idx >> 3) & 255, seg = idx & 7;
            const uint32_t* gsrc = (hl ? g_wbl : g_wbh) + n * 576 + seg * 4;
            uint32_t saddr = sbase + (B_OFF + hl * B_HL_STRIDE + n * 36 + seg * 4) * 4;
            cp_async16(saddr, gsrc);
        }
        CP_COMMIT();
        const float* src = g_h1 + basei[am];
        const int* tp = tabi + akb;
#pragma unroll
        for (int j = 0; j < 16; ++j) fr[j] = src[tp[j]];
    }

    for (int ch = 0; ch < 18; ++ch) {
        const int buf = ch & 1;
        // ---- cvt + STS A(ch) ----
        {
            uint32_t* dH = sAh + am * 36 + awb;
            uint32_t* dL = sAl + am * 36 + awb;
#pragma unroll
            for (int j = 0; j < 8; ++j) {
                uint32_t lo;
                uint32_t hi = bfsplit_pack_hi(fr[2 * j], fr[2 * j + 1], lo);
                dH[j] = hi;
                dL[j] = lo;
            }
        }
        if (ch < 17) {
            // ---- prefetch B(ch+1) into other buffer ----
            const int kp0n = (ch + 1) * 32;
#pragma unroll
            for (int j = 0; j < 8; ++j) {
                int idx = tid + (j << 9);
                int hl = idx >> 11, n = (idx >> 3) & 255, seg = idx & 7;
                const uint32_t* gsrc = (hl ? g_wbl : g_wbh) + n * 576 + kp0n + seg * 4;
                uint32_t saddr = sbase + (B_OFF + (buf ^ 1) * B_BUF_STRIDE + hl * B_HL_STRIDE + n * 36 + seg * 4) * 4;
                cp_async16(saddr, gsrc);
            }
            CP_COMMIT();
            // ---- prefetch A(ch+1) gather into regs ----
            const float* src = g_h1 + basei[am];
            const int* tp = tabi + (ch + 1) * 64 + akb;
#pragma unroll
            for (int j = 0; j < 16; ++j) fr[j] = src[tp[j]];
            CP_WAIT1();
        } else {
            CP_WAIT0();
        }
        __syncthreads();

        // ---- MMA: 4 k16-steps x 16 n-subtiles x 3 terms ----
        const uint32_t* sBh = sm + B_OFF + buf * B_BUF_STRIDE;
        const uint32_t* sBl = sBh + B_HL_STRIDE;
        const uint32_t* AhR = sAh + (r0 + gi) * 36;
        const uint32_t* AlR = sAl + (r0 + gi) * 36;
#pragma unroll
        for (int s16 = 0; s16 < 4; ++s16) {
            const int kw = s16 * 8;
            uint32_t ah0 = AhR[kw + ti],          ah1 = AhR[8 * 36 + kw + ti];
            uint32_t ah2 = AhR[kw + ti + 4],      ah3 = AhR[8 * 36 + kw + ti + 4];
            uint32_t al0 = AlR[kw + ti],          al1 = AlR[8 * 36 + kw + ti];
            uint32_t al2 = AlR[kw + ti + 4],      al3 = AlR[8 * 36 + kw + ti + 4];
#pragma unroll
            for (int s = 0; s < 16; ++s) {
                const int br = (c0 + s * 8 + gi) * 36 + kw;
                uint32_t bh0 = sBh[br + ti], bh1 = sBh[br + ti + 4];
                uint32_t bl0 = sBl[br + ti], bl1 = sBl[br + ti + 4];
                asm volatile(
                    "mma.sync.aligned.m16n8k16.row.col.f32.bf16.bf16.f32 "
                    "{%0,%1,%2,%3}, {%4,%5,%6,%7}, {%8,%9}, {%0,%1,%2,%3};"
                    : "+f"(d[s][0]), "+f"(d[s][1]), "+f"(d[s][2]), "+f"(d[s][3])
                    : "r"(ah0), "r"(ah1), "r"(ah2), "r"(ah3), "r"(bh0), "r"(bh1));
                asm volatile(
                    "mma.sync.aligned.m16n8k16.row.col.f32.bf16.bf16.f32 "
                    "{%0,%1,%2,%3}, {%4,%5,%6,%7}, {%8,%9}, {%0,%1,%2,%3};"
                    : "+f"(d[s][0]), "+f"(d[s][1]), "+f"(d[s][2]), "+f"(d[s][3])
                    : "r"(ah0), "r"(ah1), "r"(ah2), "r"(ah3), "r"(bl0), "r"(bl1));
                asm volatile(
                    "mma.sync.aligned.m16n8k16.row.col.f32.bf16.bf16.f32 "
                    "{%0,%1,%2,%3}, {%4,%5,%6,%7}, {%8,%9}, {%0,%1,%2,%3};"
                    : "+f"(d[s][0]), "+f"(d[s][1]), "+f"(d[s][2]), "+f"(d[s][3])
                    : "r"(al0), "r"(al1), "r"(al2), "r"(al3), "r"(bh0), "r"(bh1));
            }
        }
        __syncthreads();
    }

    // ---- epilogue: bn + relu -> g_h2[mg][co] ----
    const int mrow0 = mt * 128 + r0 + gi;
#pragma unroll
    for (int s = 0; s < 16; ++s) {
        int cl = c0 + s * 8 + 2 * ti;
        float sc0 = ssc[cl], sc1 = ssc[cl + 1];
        float sh0 = ssh[cl], sh1 = ssh[cl + 1];
        float v0 = d[s][0] * sc0 + sh0; v0 = v0 > 0.0f ? v0 : 0.0f;
        float v1 = d[s][1] * sc1 + sh1; v1 = v1 > 0.0f ? v1 : 0.0f;
        float v2 = d[s][2] * sc0 + sh0; v2 = v2 > 0.0f ? v2 : 0.0f;
        float v3 = d[s][3] * sc1 + sh1; v3 = v3 > 0.0f ? v3 : 0.0f;
        *(float2*)(g_h2 + (size_t)mrow0 * 256 + cl)       = make_float2(v0, v1);
        *(float2*)(g_h2 + (size_t)(mrow0 + 8) * 256 + cl) = make_float2(v2, v3);
    }
}

// ---------------- conv3 (depthwise 9x9) + squash -> primary caps ----------------
__global__ void conv3_kernel(const float* __restrict__ w3, const float* __restrict__ b3)
{
    int b = blockIdx.x, c = threadIdx.x;
    const float* h2b = g_h2 + b * 81 * 256;
    float acc = 0.0f;
#pragma unroll
    for (int p = 0; p < 81; ++p)
        acc = fmaf(h2b[p * 256 + c], w3[c * 81 + p], acc);
    acc += b3[c];

    float sq = acc * acc;
    sq += __shfl_xor_sync(0xffffffffu, sq, 4);
    sq += __shfl_xor_sync(0xffffffffu, sq, 2);
    sq += __shfl_xor_sync(0xffffffffu, sq, 1);
    float nrm = sqrtf(sq);
    float t1 = 1.0f - 1.0f / (exp_matched(nrm) + EPSF);
    g_u[b * 256 + c] = t1 * (acc / (nrm + EPSF));
}

// ---------------- fccaps x3 ----------------
__device__ __forceinline__ void fccaps_layer(
    int nl, int nh, int dl, int dh, const float* __restrict__ W,
    float* sU, float* sUhat, float* sS, float* sA, int tid)
{
    int tot = nl * nh * dh;
    for (int idx = tid; idx < tot; idx += 256) {
        int i = idx / (nh * dh);
        int r = idx % (nh * dh);
        int k = r / dh, l = r % dh;
        const float* wp = W + ((i * nh + k) * dl) * dh + l;
        float a = 0.0f;
        for (int j = 0; j < dl; ++j) a = fmaf(sU[i * dl + j], wp[j * dh], a);
        sUhat[idx] = a;
    }
    __syncthreads();
    for (int idx = tid; idx < nh * dh; idx += 256) {
        int k = idx / dh, l = idx % dh;
        float s = 0.0f;
        for (int i = 0; i < nl; ++i) s += sUhat[(i * nh + k) * dh + l];
        sS[idx] = s;
    }
    __syncthreads();
    for (int idx = tid; idx < nl * nh; idx += 256) {
        int i = idx / nh, k = idx % nh;
        float a = 0.0f;
        for (int l = 0; l < dh; ++l) a = fmaf(sS[k * dh + l], sUhat[(i * nh + k) * dh + l], a);
        sA[idx] = a * INV_ATTN;
    }
    __syncthreads();
    if (tid < nl) {
        float mx = -1e30f;
        for (int k = 0; k < nh; ++k) mx = fmaxf(mx, sA[tid * nh + k]);
        float s = 0.0f;
        for (int k = 0; k < nh; ++k) { float e = expf(sA[tid * nh + k] - mx); sA[tid * nh + k] = e; s += e; }
        float is = 1.0f / s;
        for (int k = 0; k < nh; ++k) sA[tid * nh + k] *= is;
    }
    __syncthreads();
    for (int idx = tid; idx < nh * dh; idx += 256) {
        int k = idx / dh, l = idx % dh;
        float a = 0.0f;
        for (int i = 0; i < nl; ++i) a = fmaf(sA[i * nh + k], sUhat[(i * nh + k) * dh + l], a);
        sS[idx] = a;
    }
    __syncthreads();
    for (int idx = tid; idx < nh * dh; idx += 256) {
        int k = idx / dh;
        float nsq = 0.0f;
        for (int l = 0; l < dh; ++l) { float t = sS[k * dh + l]; nsq = fmaf(t, t, nsq); }
        float nrm = sqrtf(nsq);
        float t1 = 1.0f - 1.0f / (exp_matched(nrm) + EPSF);
        sU[idx] = t1 * (sS[idx] / (nrm + EPSF));
    }
    __syncthreads();
}

__global__ void caps_kernel(const float* __restrict__ W1,
                            const float* __restrict__ W2,
                            const float* __restrict__ W3,
                            float* __restrict__ out)
{
    int b = blockIdx.x, tid = threadIdx.x;
    __shared__ float sU[512];
    __shared__ float sUhat[8192];
    __shared__ float sS[512];
    __shared__ float sA[1024];

    sU[tid] = g_u[b * 256 + tid];
    sU[256 + tid] = 0.0f;
    __syncthreads();

    fccaps_layer(32, 32, 8, 8, W1, sU, sUhat, sS, sA, tid);
    fccaps_layer(32, 32, 8, 8, W2, sU, sUhat, sS, sA, tid);
    fccaps_layer(32, 10, 8, 16, W3, sU, sUhat, sS, sA, tid);

    if (tid < 160) out[b * 160 + tid] = sU[tid];
}

// ---------------- launch ----------------
extern "C" void kernel_launch(void* const* d_in, const int* in_sizes, int n_in,
                              void* d_out, int out_size)
{
    const float* x       = (const float*)d_in[0];
    const float* conv1_w = (const float*)d_in[1];
    const float* conv1_b = (const float*)d_in[2];
    const float* bn1_g   = (const float*)d_in[3];
    const float* bn1_b   = (const float*)d_in[4];
    const float* bn1_m   = (const float*)d_in[5];
    const float* bn1_v   = (const float*)d_in[6];
    const float* conv2_w = (const float*)d_in[7];
    const float* conv2_b = (const float*)d_in[8];
    const float* bn2_g   = (const float*)d_in[9];
    const float* bn2_b   = (const float*)d_in[10];
    const float* bn2_m   = (const float*)d_in[11];
    const float* bn2_v   = (const float*)d_in[12];
    const float* conv3_w = (const float*)d_in[13];
    const float* conv3_b = (const float*)d_in[14];
    const float* W1      = (const float*)d_in[15];
    const float* W2      = (const float*)d_in[16];
    const float* W3      = (const float*)d_in[17];
    float* out = (float*)d_out;

    cudaFuncSetAttribute(conv2_mma_kernel, cudaFuncAttributeMaxDynamicSharedMemorySize,
                         C2_SMEM_WORDS * (int)sizeof(uint32_t));

    conv1_kernel<<<NB, 384>>>(x, conv1_w, conv1_b, bn1_g, bn1_b, bn1_m, bn1_v);
    wtrans_kernel<<<576, 256>>>(conv2_w);
    conv2_mma_kernel<<<324, 512, C2_SMEM_WORDS * sizeof(uint32_t)>>>(
        conv2_b, bn2_g, bn2_b, bn2_m, bn2_v);
    conv3_kernel<<<NB, 256>>>(conv3_w, conv3_b);
    caps_kernel<<<NB, 256>>>(W1, W2, W3, out);
}